// round 12
// baseline (speedup 1.0000x reference)
#include <cuda_runtime.h>
#include <math.h>
#include <stdint.h>

// Problem constants (fixed by setup_inputs)
#define BB 4
#define LL 2048
#define HH 8
#define DD 64
#define SS 40            // samples per query
#define UU 40            // top-k queries
#define SCALE 0.125f     // 1/sqrt(64)

// kernel1 (M measure) config
#define KM_T 512                   // threads per block
#define KM_QT 512                  // queries per block
#define KM_CH 256                  // K rows per smem chunk
#define KM_NCH (LL / KM_CH)        // 8
#define KM_BUF (KM_CH*17)          // float4 per buffer (pitch 17)
#define KM_SMEM (2*KM_BUF*16)      // 139264 B (double buffer)

// kernel3 (attention) config
#define K3_CHUNK 64
#define K3_NCH (LL / K3_CHUNK)   // 32
#define K3_T 128

// kernel4 (cumsum) config
#define K4_NC 32
#define K4_CLEN (LL / K4_NC)     // 64

// ---------------- scratch (static device globals; no runtime alloc) ----------------
__device__ float g_M[BB*HH*LL];
__device__ int   g_Mtop[BB*HH*UU];
__device__ int   g_sel[BB*HH*LL];
__device__ float g_upd[BB*HH*UU*DD];
__device__ float g_pm[BB*HH*K3_NCH*UU];
__device__ float g_pl[BB*HH*K3_NCH*UU];
__device__ float g_pacc[(size_t)BB*HH*K3_NCH*UU*DD];
__device__ float g_csum[BB*K4_NC*HH*DD];
__device__ int   g_srt[LL*SS];       // samples sorted by chunk, per query
__device__ int   g_runoff[LL*9];     // per (query, chunk) run start offsets (+ end)

__device__ __forceinline__ void cp_async16(uint32_t saddr, const void* gptr) {
    asm volatile("cp.async.cg.shared.global [%0], [%1], 16;" :: "r"(saddr), "l"(gptr));
}

// ================= Kernel 0: bin samples by K-chunk + run offsets ====
__global__ void __launch_bounds__(128) k_bin(const int* __restrict__ idx) {
    int l = blockIdx.x*128 + threadIdx.x;
    int cnt[KM_NCH];
    #pragma unroll
    for (int c = 0; c < KM_NCH; c++) cnt[c] = 0;
    int v[SS];
    #pragma unroll
    for (int s = 0; s < SS; s++) {
        v[s] = idx[l*SS + s];
        cnt[v[s] >> 8]++;
    }
    int off[KM_NCH];
    int acc = 0;
    #pragma unroll
    for (int c = 0; c < KM_NCH; c++) {
        off[c] = acc;
        g_runoff[l*9 + c] = acc;
        acc += cnt[c];
    }
    g_runoff[l*9 + 8] = acc;   // == SS
    #pragma unroll
    for (int s = 0; s < SS; s++) {
        int c = v[s] >> 8;
        g_srt[l*SS + off[c]++] = v[s];
    }
}

// ================= Kernel 1: sparsity measure M (v6: cooperative subgroup dots) ====
// Warp processes its 32 queries one at a time. 16-lane subgroups each own one sample;
// lane holds one float4 of the K row -> row read is 256B consecutive (conflict-free).
// Dot = 4 FFMA + 4 bfly shuffles. Per-query state split across partner lanes (X/Y),
// merged with one xor-16 shuffle at the end. K chunks double-buffered via cp.async.
__global__ void __launch_bounds__(KM_T)
k_M(const float* __restrict__ Q, const float* __restrict__ K) {
    extern __shared__ __align__(16) float4 sK4[];   // [2][KM_BUF]

    int bh = blockIdx.x >> 2;          // 4 q-tiles per (b,h)
    int qt = blockIdx.x & 3;
    int b = bh >> 3, h = bh & 7;
    int t = threadIdx.x;
    int warp = t >> 5, lane = t & 31;
    int sub = lane >> 4, l4 = lane & 15;
    int qbase = qt*KM_QT + warp*32;    // first query of this warp

    const float4* Kg = (const float4*)K;
    const float4* Qg = (const float4*)Q;
    uint32_t sbase = (uint32_t)__cvta_generic_to_shared(sK4);

    // per-lane split state: X <-> query (lane&15), Y <-> query (lane&15)+16
    float mX = -INFINITY, sX = 0.f, mY = -INFINITY, sY = 0.f;

    // preload chunk 0 into buffer 0
    #pragma unroll
    for (int it = 0; it < 8; it++) {
        int i = t + it*KM_T;
        int row = i >> 4, d4 = i & 15;
        cp_async16(sbase + (uint32_t)(row*17 + d4)*16,
                   Kg + ((size_t)(b*LL + row)*HH + h)*16 + d4);
    }
    asm volatile("cp.async.commit_group;");

    for (int c = 0; c < KM_NCH; c++) {
        int cur = c & 1;
        if (c < KM_NCH-1) {
            int nxt = (c+1) & 1;
            #pragma unroll
            for (int it = 0; it < 8; it++) {
                int i = t + it*KM_T;
                int row = i >> 4, d4 = i & 15;
                cp_async16(sbase + (uint32_t)(nxt*KM_BUF + row*17 + d4)*16,
                           Kg + ((size_t)(b*LL + (c+1)*KM_CH + row)*HH + h)*16 + d4);
            }
            asm volatile("cp.async.commit_group;");
            asm volatile("cp.async.wait_group 1;");
        } else {
            asm volatile("cp.async.wait_group 0;");
        }
        __syncthreads();

        const float4* buf = sK4 + cur*KM_BUF;

        // run bounds for all 32 queries of this warp (lane q holds query qbase+q's)
        int rbv = g_runoff[(qbase + lane)*9 + c];
        int rev = g_runoff[(qbase + lane)*9 + c + 1];

        // prefetch query 0
        int rb = __shfl_sync(0xffffffffu, rbv, 0);
        int re = __shfl_sync(0xffffffffu, rev, 0);
        float4 qv = Qg[((size_t)(b*LL + qbase)*HH + h)*16 + l4];
        int ji = rb + lane; if (ji > SS-1) ji = SS-1;
        int jreg = g_srt[qbase*SS + ji];

        for (int qi = 0; qi < 32; qi++) {
            int len = re - rb;
            // prefetch next query's data
            int rbN = 0, reN = 0, jregN = 0;
            float4 qvN = qv;
            if (qi < 31) {
                rbN = __shfl_sync(0xffffffffu, rbv, qi+1);
                reN = __shfl_sync(0xffffffffu, rev, qi+1);
                int lN = qbase + qi + 1;
                qvN = Qg[((size_t)(b*LL + lN)*HH + h)*16 + l4];
                int jiN = rbN + lane; if (jiN > SS-1) jiN = SS-1;
                jregN = g_srt[lN*SS + jiN];
            }

            int np = (len < 32) ? len : 32;
            for (int p = 0; p < np; p += 2) {
                int j0 = __shfl_sync(0xffffffffu, jreg, p);
                int p1 = (p+1 < np) ? p+1 : p;
                int j1 = __shfl_sync(0xffffffffu, jreg, p1);
                int j  = sub ? j1 : j0;
                float4 kv = buf[(j & 255)*17 + l4];
                float d = qv.x*kv.x + qv.y*kv.y + qv.z*kv.z + qv.w*kv.w;
                d += __shfl_xor_sync(0xffffffffu, d, 1);
                d += __shfl_xor_sync(0xffffffffu, d, 2);
                d += __shfl_xor_sync(0xffffffffu, d, 4);
                d += __shfl_xor_sync(0xffffffffu, d, 8);
                bool valid = (sub == 0) || (p+1 < np);
                bool mine  = ((lane & 15) == (qi & 15)) && valid;
                if (mine) {
                    if (qi < 16) { mX = fmaxf(mX, d); sX += d; }
                    else         { mY = fmaxf(mY, d); sY += d; }
                }
            }
            if (len > 32) {           // astronomically rare; correctness guard
                int l0 = qbase + qi;
                int jiB = rb + 32 + lane; if (jiB > SS-1) jiB = SS-1;
                int jregB = g_srt[l0*SS + jiB];
                for (int p = 32; p < len; p += 2) {
                    int j0 = __shfl_sync(0xffffffffu, jregB, p-32);
                    int p1 = (p+1 < len) ? p+1-32 : p-32;
                    int j1 = __shfl_sync(0xffffffffu, jregB, p1);
                    int j  = sub ? j1 : j0;
                    float4 kv = buf[(j & 255)*17 + l4];
                    float d = qv.x*kv.x + qv.y*kv.y + qv.z*kv.z + qv.w*kv.w;
                    d += __shfl_xor_sync(0xffffffffu, d, 1);
                    d += __shfl_xor_sync(0xffffffffu, d, 2);
                    d += __shfl_xor_sync(0xffffffffu, d, 4);
                    d += __shfl_xor_sync(0xffffffffu, d, 8);
                    bool valid = (sub == 0) || (p+1 < len);
                    bool mine  = ((lane & 15) == (qi & 15)) && valid;
                    if (mine) {
                        if (qi < 16) { mX = fmaxf(mX, d); sX += d; }
                        else         { mY = fmaxf(mY, d); sY += d; }
                    }
                }
            }
            rb = rbN; re = reN; qv = qvN; jreg = jregN;
        }
        __syncthreads();      // all warps done with buf before it is overwritten
    }

    // merge partner-lane halves and write
    float mXo = __shfl_xor_sync(0xffffffffu, mX, 16);
    float sXo = __shfl_xor_sync(0xffffffffu, sX, 16);
    float mYo = __shfl_xor_sync(0xffffffffu, mY, 16);
    float sYo = __shfl_xor_sync(0xffffffffu, sY, 16);
    float mF = (lane < 16) ? fmaxf(mX, mXo) : fmaxf(mY, mYo);
    float sF = (lane < 16) ? (sX + sXo)     : (sY + sYo);
    g_M[bh*LL + qbase + lane] = mF - sF * (1.0f/(float)LL);
}

// ================= Kernel 2: top-U per (b,h) ====
__global__ void __launch_bounds__(256) k_topk() {
    int bh = blockIdx.x;
    int t = threadIdx.x;
    int lane = t & 31, w = t >> 5;
    float v[8];
    __shared__ float rv[8];
    __shared__ int   ri[8];
    __shared__ int   ssel;
    #pragma unroll
    for (int j = 0; j < 8; j++) {
        int i = t + 256*j;
        v[j] = g_M[bh*LL + i];
        g_sel[bh*LL + i] = -1;
    }
    for (int u = 0; u < UU; u++) {
        float lv = v[0]; int li = t;
        #pragma unroll
        for (int j = 1; j < 8; j++)
            if (v[j] > lv) { lv = v[j]; li = t + 256*j; }
        #pragma unroll
        for (int off = 16; off; off >>= 1) {
            float ov = __shfl_xor_sync(0xffffffffu, lv, off);
            int   oi = __shfl_xor_sync(0xffffffffu, li, off);
            if (ov > lv || (ov == lv && oi < li)) { lv = ov; li = oi; }
        }
        if (lane == 0) { rv[w] = lv; ri[w] = li; }
        __syncthreads();
        if (t == 0) {
            float bv = rv[0]; int bi = ri[0];
            #pragma unroll
            for (int k = 1; k < 8; k++)
                if (rv[k] > bv || (rv[k] == bv && ri[k] < bi)) { bv = rv[k]; bi = ri[k]; }
            ssel = bi;
            g_Mtop[bh*UU + u] = bi;
            g_sel[bh*LL + bi] = u;
        }
        __syncthreads();
        int sel = ssel;
        if ((sel & 255) == t) v[sel >> 8] = -INFINITY;
    }
}

// ================= Kernel 3: split-K attention partials ====
__global__ void __launch_bounds__(K3_T)
k_attn_partial(const float* __restrict__ Q, const float* __restrict__ K,
               const float* __restrict__ V) {
    __shared__ __align__(16) float Qs[UU*68];
    __shared__ __align__(16) float Ks[K3_CHUNK*68];
    __shared__ __align__(16) float psm[K3_CHUNK*44];
    __shared__ float sm_m[UU];

    int c = blockIdx.x, bh = blockIdx.y;
    int b = bh >> 3, h = bh & 7;
    int tid = threadIdx.x;
    int k0 = c * K3_CHUNK;
    const float4* Qg = (const float4*)Q;
    const float4* Kg = (const float4*)K;
    const float4* Vg = (const float4*)V;
    float4* Qs4 = (float4*)Qs;
    float4* Ks4 = (float4*)Ks;

    #pragma unroll
    for (int it = 0; it < 5; it++) {
        int i = tid + it*128;
        int u = i >> 4, d4 = i & 15;
        int l = g_Mtop[bh*UU + u];
        Qs4[u*17 + d4] = Qg[((b*LL + l)*HH + h)*16 + d4];
    }
    #pragma unroll
    for (int it = 0; it < 8; it++) {
        int i = tid + it*128;
        int k = i >> 4, d4 = i & 15;
        Ks4[k*17 + d4] = Kg[((b*LL + k0 + k)*HH + h)*16 + d4];
    }
    __syncthreads();

    // ---- scores ----
    {
        int ug = tid & 7, kg = tid >> 3;
        float acc[4][5];
        #pragma unroll
        for (int a = 0; a < 4; a++)
            #pragma unroll
            for (int q = 0; q < 5; q++) acc[a][q] = 0.f;
        #pragma unroll
        for (int d4 = 0; d4 < 16; d4++) {
            float4 kv[4], qv[5];
            #pragma unroll
            for (int a = 0; a < 4; a++) kv[a] = Ks4[(kg*4 + a)*17 + d4];
            #pragma unroll
            for (int q = 0; q < 5; q++) qv[q] = Qs4[(ug*5 + q)*17 + d4];
            #pragma unroll
            for (int a = 0; a < 4; a++)
                #pragma unroll
                for (int q = 0; q < 5; q++)
                    acc[a][q] += kv[a].x*qv[q].x + kv[a].y*qv[q].y
                               + kv[a].z*qv[q].z + kv[a].w*qv[q].w;
        }
        #pragma unroll
        for (int a = 0; a < 4; a++)
            #pragma unroll
            for (int q = 0; q < 5; q++)
                psm[(kg*4 + a)*44 + ug*5 + q] = acc[a][q] * SCALE;
    }
    __syncthreads();

    if (tid < UU) {
        float m = -INFINITY;
        #pragma unroll 8
        for (int k = 0; k < K3_CHUNK; k++) m = fmaxf(m, psm[k*44 + tid]);
        sm_m[tid] = m;
    }
    __syncthreads();
    #pragma unroll
    for (int it = 0; it < 20; it++) {
        int i = tid + it*128;
        int k = i / 40, u = i - k*40;
        psm[k*44 + u] = __expf(psm[k*44 + u] - sm_m[u]);
    }
    __syncthreads();

    #pragma unroll
    for (int it = 0; it < 8; it++) {
        int i = tid + it*128;
        int k = i >> 4, d4 = i & 15;
        Ks4[k*17 + d4] = Vg[((b*LL + k0 + k)*HH + h)*16 + d4];
    }
    if (tid < UU) {
        float s = 0.f;
        #pragma unroll 8
        for (int k = 0; k < K3_CHUNK; k++) s += psm[k*44 + tid];
        int pidx = (bh*K3_NCH + c)*UU + tid;
        g_pm[pidx] = sm_m[tid];
        g_pl[pidx] = s;
    }
    __syncthreads();

    // ---- AV ----
    {
        int dg = tid & 15, ug = tid >> 4;
        float4 oacc[5];
        #pragma unroll
        for (int j = 0; j < 5; j++) oacc[j] = make_float4(0.f, 0.f, 0.f, 0.f);
        #pragma unroll 8
        for (int k = 0; k < K3_CHUNK; k++) {
            float4 vv = Ks4[k*17 + dg];
            float p[5];
            #pragma unroll
            for (int j = 0; j < 5; j++) p[j] = psm[k*44 + ug*5 + j];
            #pragma unroll
            for (int j = 0; j < 5; j++) {
                oacc[j].x += p[j]*vv.x; oacc[j].y += p[j]*vv.y;
                oacc[j].z += p[j]*vv.z; oacc[j].w += p[j]*vv.w;
            }
        }
        float4* dst = (float4*)(g_pacc + ((size_t)(bh*K3_NCH + c)*UU)*DD);
        #pragma unroll
        for (int j = 0; j < 5; j++)
            dst[(ug*5 + j)*16 + dg] = oacc[j];
    }
}

// ================= Kernel 3b: LSE combine (8 u per block, MLP-8) ====
__global__ void __launch_bounds__(512) k_combine() {
    int bh = blockIdx.x / 5;
    int u  = (blockIdx.x % 5)*8 + (threadIdx.x >> 6);
    int d  = threadIdx.x & 63;
    int base = bh*K3_NCH*UU + u;
    float m = -INFINITY;
    #pragma unroll
    for (int c = 0; c < K3_NCH; c++) m = fmaxf(m, g_pm[base + c*UU]);
    float ls = 0.f;
    float vacc[8];
    #pragma unroll
    for (int j = 0; j < 8; j++) vacc[j] = 0.f;
    #pragma unroll
    for (int c = 0; c < K3_NCH; c += 8) {
        float w[8], pl[8], pv[8];
        #pragma unroll
        for (int j = 0; j < 8; j++) w[j]  = __expf(g_pm[base + (c+j)*UU] - m);
        #pragma unroll
        for (int j = 0; j < 8; j++) pl[j] = g_pl[base + (c+j)*UU];
        #pragma unroll
        for (int j = 0; j < 8; j++) pv[j] = g_pacc[(size_t)(base + (c+j)*UU)*DD + d];
        #pragma unroll
        for (int j = 0; j < 8; j++) { ls += pl[j]*w[j]; vacc[j] += pv[j]*w[j]; }
    }
    float val = ((vacc[0]+vacc[1]) + (vacc[2]+vacc[3]))
              + ((vacc[4]+vacc[5]) + (vacc[6]+vacc[7]));
    g_upd[(bh*UU + u)*DD + d] = val / ls;
}

// ================= Kernel 4a: per-chunk sums of V along L (MLP-8) ====
__global__ void __launch_bounds__(512) k_csum(const float* __restrict__ V) {
    int b = blockIdx.x >> 5;
    int c = blockIdx.x & 31;
    int hd = threadIdx.x;
    const float* p = V + ((size_t)(b*LL + c*K4_CLEN))*512 + hd;
    float s0 = 0.f, s1 = 0.f, s2 = 0.f, s3 = 0.f;
    #pragma unroll
    for (int i = 0; i < K4_CLEN; i += 8) {
        float v0 = p[(i+0)*512], v1 = p[(i+1)*512];
        float v2 = p[(i+2)*512], v3 = p[(i+3)*512];
        float v4 = p[(i+4)*512], v5 = p[(i+5)*512];
        float v6 = p[(i+6)*512], v7 = p[(i+7)*512];
        s0 += v0 + v4; s1 += v1 + v5; s2 += v2 + v6; s3 += v3 + v7;
    }
    g_csum[(b*K4_NC + c)*512 + hd] = (s0 + s1) + (s2 + s3);
}

// ================= Kernel 4b: cumsum + scatter upd -> output (MLP-8 batches) ====
__global__ void __launch_bounds__(512) k_out(const float* __restrict__ V,
                                             float* __restrict__ out) {
    int b = blockIdx.x >> 5;
    int c = blockIdx.x & 31;
    int hd = threadIdx.x;
    int h = hd >> 6, d = hd & 63;
    float acc = 0.f;
    #pragma unroll
    for (int cc = 0; cc < K4_NC - 1; cc++) {
        float vv = g_csum[(b*K4_NC + cc)*512 + hd];
        if (cc < c) acc += vv;
    }
    const float* p = V   + ((size_t)(b*LL + c*K4_CLEN))*512 + hd;
    float*       q = out + ((size_t)(b*LL + c*K4_CLEN))*512 + hd;
    const int* sel = g_sel + (b*HH + h)*LL + c*K4_CLEN;
    #pragma unroll
    for (int i0 = 0; i0 < K4_CLEN; i0 += 8) {
        float v[8]; int se[8];
        #pragma unroll
        for (int j = 0; j < 8; j++) v[j] = p[(i0+j)*512];
        #pragma unroll
        for (int j = 0; j < 8; j++) se[j] = sel[i0+j];
        #pragma unroll
        for (int j = 0; j < 8; j++) {
            acc += v[j];
            float o = acc;
            if (se[j] >= 0) o = g_upd[((b*HH + h)*UU + se[j])*DD + d];
            q[(i0+j)*512] = o;
        }
    }
}

// ================= launch ====
extern "C" void kernel_launch(void* const* d_in, const int* in_sizes, int n_in,
                              void* d_out, int out_size) {
    const float* Q  = (const float*)d_in[0];
    const float* K  = (const float*)d_in[1];
    const float* V  = (const float*)d_in[2];
    const int* idx  = (const int*)d_in[3];
    float* out = (float*)d_out;

    cudaFuncSetAttribute(k_M, cudaFuncAttributeMaxDynamicSharedMemorySize, KM_SMEM);

    k_bin<<<LL/128, 128>>>(idx);
    k_M<<<BB*HH*(LL/KM_QT), KM_T, KM_SMEM>>>(Q, K);
    k_topk<<<BB*HH, 256>>>();
    dim3 g3(K3_NCH, BB*HH);
    k_attn_partial<<<g3, K3_T>>>(Q, K, V);
    k_combine<<<BB*HH*(UU/8), 512>>>();
    k_csum<<<BB*K4_NC, 512>>>(V);
    k_out<<<BB*K4_NC, 512>>>(V, out);
}

// round 13
// speedup vs baseline: 1.3409x; 1.3409x over previous
#include <cuda_runtime.h>
#include <math.h>
#include <stdint.h>

// Problem constants (fixed by setup_inputs)
#define BB 4
#define LL 2048
#define HH 8
#define DD 64
#define SS 40            // samples per query
#define UU 40            // top-k queries
#define SCALE 0.125f     // 1/sqrt(64)

// kernel1 (M measure) config
#define KM_T 512                   // threads per block
#define KM_QT 512
#define KM_CH 256                  // K rows per smem chunk
#define KM_NCH (LL / KM_CH)        // 8
#define KM_BUF (KM_CH*17)          // float4 per buffer (pitch 17)
#define KM_SMEM (2*KM_BUF*16)      // 139264 B (double buffer)

// kernel3 (attention) config
#define K3_CHUNK 128
#define K3_NCH (LL / K3_CHUNK)   // 16
#define K3_T 128
// dynamic smem: Qs 40*17 f4 + Ks 128*17 f4 + psm 128*44 fl + sm_m 40 fl
#define K3_Q4   (UU*17)            // 680 float4
#define K3_K4   (K3_CHUNK*17)      // 2176 float4
#define K3_PSM  (K3_CHUNK*44)      // 5632 floats
#define K3_SMEM ((K3_Q4 + K3_K4)*16 + (K3_PSM + UU)*4)   // 68384 B

// kernel4 (cumsum) config
#define K4_NC 32
#define K4_CLEN (LL / K4_NC)     // 64

// ---------------- scratch (static device globals; no runtime alloc) ----------------
__device__ float g_M[BB*HH*LL];
__device__ int   g_Mtop[BB*HH*UU];
__device__ int   g_sel[BB*HH*LL];
__device__ float g_upd[BB*HH*UU*DD];
__device__ float g_pm[BB*HH*K3_NCH*UU];
__device__ float g_pl[BB*HH*K3_NCH*UU];
__device__ float g_pacc[(size_t)BB*HH*K3_NCH*UU*DD];
__device__ float g_csum[BB*K4_NC*HH*DD];
__device__ int   g_srt[LL*SS];     // samples sorted by chunk, per query (shared over bh)

__device__ __forceinline__ void cp_async16(uint32_t saddr, const void* gptr) {
    asm volatile("cp.async.cg.shared.global [%0], [%1], 16;" :: "r"(saddr), "l"(gptr));
}

// ================= Kernel 0: bin samples by K-chunk ====
__global__ void __launch_bounds__(128) k_bin(const int* __restrict__ idx) {
    int l = blockIdx.x*128 + threadIdx.x;
    int cnt[KM_NCH];
    #pragma unroll
    for (int c = 0; c < KM_NCH; c++) cnt[c] = 0;
    int v[SS];
    #pragma unroll
    for (int s = 0; s < SS; s++) {
        v[s] = idx[l*SS + s];
        cnt[v[s] >> 8]++;
    }
    int off[KM_NCH];
    int acc = 0;
    #pragma unroll
    for (int c = 0; c < KM_NCH; c++) { off[c] = acc; acc += cnt[c]; }
    #pragma unroll
    for (int s = 0; s < SS; s++) {
        int c = v[s] >> 8;
        g_srt[l*SS + off[c]++] = v[s];
    }
}

// ================= Kernel 1: sparsity measure M (v5: chunk-resident K, sorted runs,
// cp.async double buffer, single wave) — best measured variant, reverted exactly ====
__global__ void __launch_bounds__(KM_T)
k_M(const float* __restrict__ Q, const float* __restrict__ K) {
    extern __shared__ __align__(16) float4 sK4[];   // [2][KM_BUF]

    int bh = blockIdx.x >> 2;          // 4 q-tiles per (b,h)
    int qt = blockIdx.x & 3;
    int b = bh >> 3, h = bh & 7;
    int t = threadIdx.x;
    int l = qt*KM_QT + t;

    const float4* qrow = (const float4*)Q + ((size_t)(b*LL + l)*HH + h)*16;
    float4 q[16];
    #pragma unroll
    for (int i = 0; i < 16; i++) q[i] = qrow[i];

    const int* srt = g_srt + l*SS;
    int r = 0;
    int jn = srt[0];

    const float4* Kg = (const float4*)K;
    uint32_t sbase = (uint32_t)__cvta_generic_to_shared(sK4);
    float maxv = -INFINITY, sum = 0.f;

    // preload chunk 0 into buffer 0
    #pragma unroll
    for (int it = 0; it < 8; it++) {
        int i = t + it*KM_T;
        int row = i >> 4, d4 = i & 15;
        cp_async16(sbase + (uint32_t)(row*17 + d4)*16,
                   Kg + ((size_t)(b*LL + row)*HH + h)*16 + d4);
    }
    asm volatile("cp.async.commit_group;");

    for (int c = 0; c < KM_NCH; c++) {
        int cur = c & 1;
        if (c < KM_NCH-1) {
            int nxt = (c+1) & 1;
            #pragma unroll
            for (int it = 0; it < 8; it++) {
                int i = t + it*KM_T;
                int row = i >> 4, d4 = i & 15;
                cp_async16(sbase + (uint32_t)(nxt*KM_BUF + row*17 + d4)*16,
                           Kg + ((size_t)(b*LL + (c+1)*KM_CH + row)*HH + h)*16 + d4);
            }
            asm volatile("cp.async.commit_group;");
            asm volatile("cp.async.wait_group 1;");
        } else {
            asm volatile("cp.async.wait_group 0;");
        }
        __syncthreads();

        const float4* buf = sK4 + cur*KM_BUF;
        while ((jn >> 8) == c) {
            const float4* kr = buf + (jn & 255)*17;
            float4 a = make_float4(0.f, 0.f, 0.f, 0.f);
            #pragma unroll
            for (int d4 = 0; d4 < 16; d4++) {
                float4 kv = kr[d4];
                a.x += q[d4].x*kv.x; a.y += q[d4].y*kv.y;
                a.z += q[d4].z*kv.z; a.w += q[d4].w*kv.w;
            }
            float dot = (a.x + a.y) + (a.z + a.w);
            maxv = fmaxf(maxv, dot);
            sum += dot;
            r++;
            jn = (r < SS) ? srt[r] : 0x7fffffff;
        }
        __syncthreads();
    }
    g_M[bh*LL + l] = maxv - sum * (1.0f/(float)LL);
}

// ================= Kernel 2: top-U per (b,h) ====
__global__ void __launch_bounds__(256) k_topk() {
    int bh = blockIdx.x;
    int t = threadIdx.x;
    int lane = t & 31, w = t >> 5;
    float v[8];
    __shared__ float rv[8];
    __shared__ int   ri[8];
    __shared__ int   ssel;
    #pragma unroll
    for (int j = 0; j < 8; j++) {
        int i = t + 256*j;
        v[j] = g_M[bh*LL + i];
        g_sel[bh*LL + i] = -1;
    }
    for (int u = 0; u < UU; u++) {
        float lv = v[0]; int li = t;
        #pragma unroll
        for (int j = 1; j < 8; j++)
            if (v[j] > lv) { lv = v[j]; li = t + 256*j; }
        #pragma unroll
        for (int off = 16; off; off >>= 1) {
            float ov = __shfl_xor_sync(0xffffffffu, lv, off);
            int   oi = __shfl_xor_sync(0xffffffffu, li, off);
            if (ov > lv || (ov == lv && oi < li)) { lv = ov; li = oi; }
        }
        if (lane == 0) { rv[w] = lv; ri[w] = li; }
        __syncthreads();
        if (t == 0) {
            float bv = rv[0]; int bi = ri[0];
            #pragma unroll
            for (int k = 1; k < 8; k++)
                if (rv[k] > bv || (rv[k] == bv && ri[k] < bi)) { bv = rv[k]; bi = ri[k]; }
            ssel = bi;
            g_Mtop[bh*UU + u] = bi;
            g_sel[bh*LL + bi] = u;
        }
        __syncthreads();
        int sel = ssel;
        if ((sel & 255) == t) v[sel >> 8] = -INFINITY;
    }
}

// ================= Kernel 3: split-K attention partials (v2: 128-row chunks,
// 8k x 5u register tiles -> 13 LDS.128 per 160 FFMA) ====
__global__ void __launch_bounds__(K3_T)
k_attn_partial(const float* __restrict__ Q, const float* __restrict__ K,
               const float* __restrict__ V) {
    extern __shared__ __align__(16) float4 a_smem[];
    float4* Qs4 = a_smem;                  // UU*17
    float4* Ks4 = a_smem + K3_Q4;          // K3_CHUNK*17
    float*  psm = (float*)(a_smem + K3_Q4 + K3_K4);   // K3_CHUNK*44
    float*  sm_m = psm + K3_PSM;           // UU

    int c = blockIdx.x, bh = blockIdx.y;
    int b = bh >> 3, h = bh & 7;
    int tid = threadIdx.x;
    int k0 = c * K3_CHUNK;
    const float4* Qg = (const float4*)Q;
    const float4* Kg = (const float4*)K;
    const float4* Vg = (const float4*)V;

    #pragma unroll
    for (int it = 0; it < 5; it++) {                  // Q_reduce: 640 f4
        int i = tid + it*128;
        int u = i >> 4, d4 = i & 15;
        int l = g_Mtop[bh*UU + u];
        Qs4[u*17 + d4] = Qg[((b*LL + l)*HH + h)*16 + d4];
    }
    #pragma unroll
    for (int it = 0; it < 16; it++) {                 // K chunk: 2048 f4
        int i = tid + it*128;
        int k = i >> 4, d4 = i & 15;
        Ks4[k*17 + d4] = Kg[((b*LL + k0 + k)*HH + h)*16 + d4];
    }
    __syncthreads();

    // ---- scores: thread = (ug=tid&7 -> 5 u, kg=tid>>3 -> 8 k) ----
    {
        int ug = tid & 7, kg = tid >> 3;
        float acc[8][5];
        #pragma unroll
        for (int a = 0; a < 8; a++)
            #pragma unroll
            for (int q = 0; q < 5; q++) acc[a][q] = 0.f;
        #pragma unroll
        for (int d4 = 0; d4 < 16; d4++) {
            float4 kv[8], qv[5];
            #pragma unroll
            for (int a = 0; a < 8; a++) kv[a] = Ks4[(kg*8 + a)*17 + d4];
            #pragma unroll
            for (int q = 0; q < 5; q++) qv[q] = Qs4[(ug*5 + q)*17 + d4];
            #pragma unroll
            for (int a = 0; a < 8; a++)
                #pragma unroll
                for (int q = 0; q < 5; q++)
                    acc[a][q] += kv[a].x*qv[q].x + kv[a].y*qv[q].y
                               + kv[a].z*qv[q].z + kv[a].w*qv[q].w;
        }
        #pragma unroll
        for (int a = 0; a < 8; a++)
            #pragma unroll
            for (int q = 0; q < 5; q++)
                psm[(kg*8 + a)*44 + ug*5 + q] = acc[a][q] * SCALE;
    }
    __syncthreads();

    if (tid < UU) {
        float m = -INFINITY;
        #pragma unroll 8
        for (int k = 0; k < K3_CHUNK; k++) m = fmaxf(m, psm[k*44 + tid]);
        sm_m[tid] = m;
    }
    __syncthreads();
    #pragma unroll
    for (int it = 0; it < 40; it++) {                 // 5120 exps
        int i = tid + it*128;
        int k = i / 40, u = i - k*40;
        psm[k*44 + u] = __expf(psm[k*44 + u] - sm_m[u]);
    }
    __syncthreads();

    #pragma unroll
    for (int it = 0; it < 16; it++) {                 // V chunk (reuse Ks)
        int i = tid + it*128;
        int k = i >> 4, d4 = i & 15;
        Ks4[k*17 + d4] = Vg[((b*LL + k0 + k)*HH + h)*16 + d4];
    }
    if (tid < UU) {
        float s = 0.f;
        #pragma unroll 8
        for (int k = 0; k < K3_CHUNK; k++) s += psm[k*44 + tid];
        int pidx = (bh*K3_NCH + c)*UU + tid;
        g_pm[pidx] = sm_m[tid];
        g_pl[pidx] = s;
    }
    __syncthreads();

    // ---- AV: thread = (dg=tid&15 -> 1 f4 of d, ug=tid>>4 -> 5 u), full k range ----
    {
        int dg = tid & 15, ug = tid >> 4;
        float4 oacc[5];
        #pragma unroll
        for (int j = 0; j < 5; j++) oacc[j] = make_float4(0.f, 0.f, 0.f, 0.f);
        #pragma unroll 8
        for (int k = 0; k < K3_CHUNK; k++) {
            float4 vv = Ks4[k*17 + dg];
            float p[5];
            #pragma unroll
            for (int j = 0; j < 5; j++) p[j] = psm[k*44 + ug*5 + j];
            #pragma unroll
            for (int j = 0; j < 5; j++) {
                oacc[j].x += p[j]*vv.x; oacc[j].y += p[j]*vv.y;
                oacc[j].z += p[j]*vv.z; oacc[j].w += p[j]*vv.w;
            }
        }
        float4* dst = (float4*)(g_pacc + ((size_t)(bh*K3_NCH + c)*UU)*DD);
        #pragma unroll
        for (int j = 0; j < 5; j++)
            dst[(ug*5 + j)*16 + dg] = oacc[j];
    }
}

// ================= Kernel 3b: LSE combine (8 u per block, MLP-8) ====
__global__ void __launch_bounds__(512) k_combine() {
    int bh = blockIdx.x / 5;
    int u  = (blockIdx.x % 5)*8 + (threadIdx.x >> 6);
    int d  = threadIdx.x & 63;
    int base = bh*K3_NCH*UU + u;
    float m = -INFINITY;
    #pragma unroll
    for (int c = 0; c < K3_NCH; c++) m = fmaxf(m, g_pm[base + c*UU]);
    float ls = 0.f;
    float vacc[8];
    #pragma unroll
    for (int j = 0; j < 8; j++) vacc[j] = 0.f;
    #pragma unroll
    for (int c = 0; c < K3_NCH; c += 8) {
        float w[8], pl[8], pv[8];
        #pragma unroll
        for (int j = 0; j < 8; j++) w[j]  = __expf(g_pm[base + (c+j)*UU] - m);
        #pragma unroll
        for (int j = 0; j < 8; j++) pl[j] = g_pl[base + (c+j)*UU];
        #pragma unroll
        for (int j = 0; j < 8; j++) pv[j] = g_pacc[(size_t)(base + (c+j)*UU)*DD + d];
        #pragma unroll
        for (int j = 0; j < 8; j++) { ls += pl[j]*w[j]; vacc[j] += pv[j]*w[j]; }
    }
    float val = ((vacc[0]+vacc[1]) + (vacc[2]+vacc[3]))
              + ((vacc[4]+vacc[5]) + (vacc[6]+vacc[7]));
    g_upd[(bh*UU + u)*DD + d] = val / ls;
}

// ================= Kernel 4a: per-chunk sums of V along L (MLP-8) ====
__global__ void __launch_bounds__(512) k_csum(const float* __restrict__ V) {
    int b = blockIdx.x >> 5;
    int c = blockIdx.x & 31;
    int hd = threadIdx.x;
    const float* p = V + ((size_t)(b*LL + c*K4_CLEN))*512 + hd;
    float s0 = 0.f, s1 = 0.f, s2 = 0.f, s3 = 0.f;
    #pragma unroll
    for (int i = 0; i < K4_CLEN; i += 8) {
        float v0 = p[(i+0)*512], v1 = p[(i+1)*512];
        float v2 = p[(i+2)*512], v3 = p[(i+3)*512];
        float v4 = p[(i+4)*512], v5 = p[(i+5)*512];
        float v6 = p[(i+6)*512], v7 = p[(i+7)*512];
        s0 += v0 + v4; s1 += v1 + v5; s2 += v2 + v6; s3 += v3 + v7;
    }
    g_csum[(b*K4_NC + c)*512 + hd] = (s0 + s1) + (s2 + s3);
}

// ================= Kernel 4b: cumsum + scatter upd -> output (MLP-8 batches) ====
__global__ void __launch_bounds__(512) k_out(const float* __restrict__ V,
                                             float* __restrict__ out) {
    int b = blockIdx.x >> 5;
    int c = blockIdx.x & 31;
    int hd = threadIdx.x;
    int h = hd >> 6, d = hd & 63;
    float acc = 0.f;
    #pragma unroll
    for (int cc = 0; cc < K4_NC - 1; cc++) {
        float vv = g_csum[(b*K4_NC + cc)*512 + hd];
        if (cc < c) acc += vv;
    }
    const float* p = V   + ((size_t)(b*LL + c*K4_CLEN))*512 + hd;
    float*       q = out + ((size_t)(b*LL + c*K4_CLEN))*512 + hd;
    const int* sel = g_sel + (b*HH + h)*LL + c*K4_CLEN;
    #pragma unroll
    for (int i0 = 0; i0 < K4_CLEN; i0 += 8) {
        float v[8]; int se[8];
        #pragma unroll
        for (int j = 0; j < 8; j++) v[j] = p[(i0+j)*512];
        #pragma unroll
        for (int j = 0; j < 8; j++) se[j] = sel[i0+j];
        #pragma unroll
        for (int j = 0; j < 8; j++) {
            acc += v[j];
            float o = acc;
            if (se[j] >= 0) o = g_upd[((b*HH + h)*UU + se[j])*DD + d];
            q[(i0+j)*512] = o;
        }
    }
}

// ================= launch ====
extern "C" void kernel_launch(void* const* d_in, const int* in_sizes, int n_in,
                              void* d_out, int out_size) {
    const float* Q  = (const float*)d_in[0];
    const float* K  = (const float*)d_in[1];
    const float* V  = (const float*)d_in[2];
    const int* idx  = (const int*)d_in[3];
    float* out = (float*)d_out;

    cudaFuncSetAttribute(k_M, cudaFuncAttributeMaxDynamicSharedMemorySize, KM_SMEM);
    cudaFuncSetAttribute(k_attn_partial,
                         cudaFuncAttributeMaxDynamicSharedMemorySize, K3_SMEM);

    k_bin<<<LL/128, 128>>>(idx);
    k_M<<<BB*HH*(LL/KM_QT), KM_T, KM_SMEM>>>(Q, K);
    k_topk<<<BB*HH, 256>>>();
    dim3 g3(K3_NCH, BB*HH);
    k_attn_partial<<<g3, K3_T, K3_SMEM>>>(Q, K, V);
    k_combine<<<BB*HH*(UU/8), 512>>>();
    k_csum<<<BB*K4_NC, 512>>>(V);
    k_out<<<BB*K4_NC, 512>>>(V, out);
}

// round 14
// speedup vs baseline: 1.4211x; 1.0598x over previous
#include <cuda_runtime.h>
#include <math.h>
#include <stdint.h>

// Problem constants (fixed by setup_inputs)
#define BB 4
#define LL 2048
#define HH 8
#define DD 64
#define SS 40            // samples per query
#define UU 40            // top-k queries
#define SCALE 0.125f     // 1/sqrt(64)

// kernel1 (M measure) config
#define KM_T 512                   // threads per block
#define KM_QT 512
#define KM_CH 256                  // K rows per smem chunk
#define KM_NCH (LL / KM_CH)        // 8
#define KM_BUF (KM_CH*17)          // float4 per buffer (pitch 17)
#define KM_SMEM (2*KM_BUF*16)      // 139264 B (double buffer)

// kernel3 (attention) config
#define K3_CHUNK 64
#define K3_NCH (LL / K3_CHUNK)   // 32
#define K3_T 128

// kernel4 (cumsum) config
#define K4_NC 32
#define K4_CLEN (LL / K4_NC)     // 64

// ---------------- scratch (static device globals; no runtime alloc) ----------------
__device__ float g_M[BB*HH*LL];
__device__ int   g_Mtop[BB*HH*UU];
__device__ int   g_sel[BB*HH*LL];
__device__ float g_upd[BB*HH*UU*DD];
__device__ float g_pm[BB*HH*K3_NCH*UU];
__device__ float g_pl[BB*HH*K3_NCH*UU];
__device__ float g_pacc[(size_t)BB*HH*K3_NCH*UU*DD];
__device__ float g_csum[BB*K4_NC*HH*DD];
__device__ int   g_srt[LL*SS];     // samples sorted by chunk, per query (shared over bh)

__device__ __forceinline__ void cp_async16(uint32_t saddr, const void* gptr) {
    asm volatile("cp.async.cg.shared.global [%0], [%1], 16;" :: "r"(saddr), "l"(gptr));
}

// ================= Kernel 0: bin samples by K-chunk ====
__global__ void __launch_bounds__(128) k_bin(const int* __restrict__ idx) {
    int l = blockIdx.x*128 + threadIdx.x;
    int cnt[KM_NCH];
    #pragma unroll
    for (int c = 0; c < KM_NCH; c++) cnt[c] = 0;
    int v[SS];
    #pragma unroll
    for (int s = 0; s < SS; s++) {
        v[s] = idx[l*SS + s];
        cnt[v[s] >> 8]++;
    }
    int off[KM_NCH];
    int acc = 0;
    #pragma unroll
    for (int c = 0; c < KM_NCH; c++) { off[c] = acc; acc += cnt[c]; }
    #pragma unroll
    for (int s = 0; s < SS; s++) {
        int c = v[s] >> 8;
        g_srt[l*SS + off[c]++] = v[s];
    }
}

// ================= Kernel 1: sparsity measure M (v5 — best measured variant) ====
__global__ void __launch_bounds__(KM_T)
k_M(const float* __restrict__ Q, const float* __restrict__ K) {
    extern __shared__ __align__(16) float4 sK4[];   // [2][KM_BUF]

    int bh = blockIdx.x >> 2;          // 4 q-tiles per (b,h)
    int qt = blockIdx.x & 3;
    int b = bh >> 3, h = bh & 7;
    int t = threadIdx.x;
    int l = qt*KM_QT + t;

    const float4* qrow = (const float4*)Q + ((size_t)(b*LL + l)*HH + h)*16;
    float4 q[16];
    #pragma unroll
    for (int i = 0; i < 16; i++) q[i] = qrow[i];

    const int* srt = g_srt + l*SS;
    int r = 0;
    int jn = srt[0];

    const float4* Kg = (const float4*)K;
    uint32_t sbase = (uint32_t)__cvta_generic_to_shared(sK4);
    float maxv = -INFINITY, sum = 0.f;

    // preload chunk 0 into buffer 0
    #pragma unroll
    for (int it = 0; it < 8; it++) {
        int i = t + it*KM_T;
        int row = i >> 4, d4 = i & 15;
        cp_async16(sbase + (uint32_t)(row*17 + d4)*16,
                   Kg + ((size_t)(b*LL + row)*HH + h)*16 + d4);
    }
    asm volatile("cp.async.commit_group;");

    for (int c = 0; c < KM_NCH; c++) {
        int cur = c & 1;
        if (c < KM_NCH-1) {
            int nxt = (c+1) & 1;
            #pragma unroll
            for (int it = 0; it < 8; it++) {
                int i = t + it*KM_T;
                int row = i >> 4, d4 = i & 15;
                cp_async16(sbase + (uint32_t)(nxt*KM_BUF + row*17 + d4)*16,
                           Kg + ((size_t)(b*LL + (c+1)*KM_CH + row)*HH + h)*16 + d4);
            }
            asm volatile("cp.async.commit_group;");
            asm volatile("cp.async.wait_group 1;");
        } else {
            asm volatile("cp.async.wait_group 0;");
        }
        __syncthreads();

        const float4* buf = sK4 + cur*KM_BUF;
        while ((jn >> 8) == c) {
            const float4* kr = buf + (jn & 255)*17;
            float4 a = make_float4(0.f, 0.f, 0.f, 0.f);
            #pragma unroll
            for (int d4 = 0; d4 < 16; d4++) {
                float4 kv = kr[d4];
                a.x += q[d4].x*kv.x; a.y += q[d4].y*kv.y;
                a.z += q[d4].z*kv.z; a.w += q[d4].w*kv.w;
            }
            float dot = (a.x + a.y) + (a.z + a.w);
            maxv = fmaxf(maxv, dot);
            sum += dot;
            r++;
            jn = (r < SS) ? srt[r] : 0x7fffffff;
        }
        __syncthreads();
    }
    g_M[bh*LL + l] = maxv - sum * (1.0f/(float)LL);
}

// ================= Kernel 2: top-U per (b,h) ====
__global__ void __launch_bounds__(256) k_topk() {
    int bh = blockIdx.x;
    int t = threadIdx.x;
    int lane = t & 31, w = t >> 5;
    float v[8];
    __shared__ float rv[8];
    __shared__ int   ri[8];
    __shared__ int   ssel;
    #pragma unroll
    for (int j = 0; j < 8; j++) {
        int i = t + 256*j;
        v[j] = g_M[bh*LL + i];
        g_sel[bh*LL + i] = -1;
    }
    for (int u = 0; u < UU; u++) {
        float lv = v[0]; int li = t;
        #pragma unroll
        for (int j = 1; j < 8; j++)
            if (v[j] > lv) { lv = v[j]; li = t + 256*j; }
        #pragma unroll
        for (int off = 16; off; off >>= 1) {
            float ov = __shfl_xor_sync(0xffffffffu, lv, off);
            int   oi = __shfl_xor_sync(0xffffffffu, li, off);
            if (ov > lv || (ov == lv && oi < li)) { lv = ov; li = oi; }
        }
        if (lane == 0) { rv[w] = lv; ri[w] = li; }
        __syncthreads();
        if (t == 0) {
            float bv = rv[0]; int bi = ri[0];
            #pragma unroll
            for (int k = 1; k < 8; k++)
                if (rv[k] > bv || (rv[k] == bv && ri[k] < bi)) { bv = rv[k]; bi = ri[k]; }
            ssel = bi;
            g_Mtop[bh*UU + u] = bi;
            g_sel[bh*LL + bi] = u;
        }
        __syncthreads();
        int sel = ssel;
        if ((sel & 255) == t) v[sel >> 8] = -INFINITY;
    }
}

// ================= Kernel 3: split-K attention partials (round-10 tiling +
// register-fused softmax: no psm rescan passes) ====
__global__ void __launch_bounds__(K3_T)
k_attn_partial(const float* __restrict__ Q, const float* __restrict__ K,
               const float* __restrict__ V) {
    __shared__ __align__(16) float Qs[UU*68];
    __shared__ __align__(16) float Ks[K3_CHUNK*68];
    __shared__ __align__(16) float psm[K3_CHUNK*44];
    __shared__ float sm_m[UU];
    __shared__ float lred[16*44];      // per-kg partial max / sum, padded rows

    int c = blockIdx.x, bh = blockIdx.y;
    int b = bh >> 3, h = bh & 7;
    int tid = threadIdx.x;
    int k0 = c * K3_CHUNK;
    const float4* Qg = (const float4*)Q;
    const float4* Kg = (const float4*)K;
    const float4* Vg = (const float4*)V;
    float4* Qs4 = (float4*)Qs;
    float4* Ks4 = (float4*)Ks;

    #pragma unroll
    for (int it = 0; it < 5; it++) {
        int i = tid + it*128;
        int u = i >> 4, d4 = i & 15;
        int l = g_Mtop[bh*UU + u];
        Qs4[u*17 + d4] = Qg[((b*LL + l)*HH + h)*16 + d4];
    }
    #pragma unroll
    for (int it = 0; it < 8; it++) {
        int i = tid + it*128;
        int k = i >> 4, d4 = i & 15;
        Ks4[k*17 + d4] = Kg[((b*LL + k0 + k)*HH + h)*16 + d4];
    }
    __syncthreads();

    int ug = tid & 7, kg = tid >> 3;
    float acc[4][5];
    // ---- scores (4k x 5u register tile; known-good 96-reg config) ----
    {
        #pragma unroll
        for (int a = 0; a < 4; a++)
            #pragma unroll
            for (int q = 0; q < 5; q++) acc[a][q] = 0.f;
        #pragma unroll
        for (int d4 = 0; d4 < 16; d4++) {
            float4 kv[4], qv[5];
            #pragma unroll
            for (int a = 0; a < 4; a++) kv[a] = Ks4[(kg*4 + a)*17 + d4];
            #pragma unroll
            for (int q = 0; q < 5; q++) qv[q] = Qs4[(ug*5 + q)*17 + d4];
            #pragma unroll
            for (int a = 0; a < 4; a++)
                #pragma unroll
                for (int q = 0; q < 5; q++)
                    acc[a][q] += kv[a].x*qv[q].x + kv[a].y*qv[q].y
                               + kv[a].z*qv[q].z + kv[a].w*qv[q].w;
        }
        #pragma unroll
        for (int a = 0; a < 4; a++)
            #pragma unroll
            for (int q = 0; q < 5; q++) acc[a][q] *= SCALE;
    }

    // ---- fused softmax: per-u max via 16-way kg reduction ----
    #pragma unroll
    for (int q = 0; q < 5; q++) {
        float lm = fmaxf(fmaxf(acc[0][q], acc[1][q]), fmaxf(acc[2][q], acc[3][q]));
        lred[kg*44 + ug*5 + q] = lm;
    }
    __syncthreads();
    if (tid < UU) {
        float m = -INFINITY;
        #pragma unroll
        for (int k = 0; k < 16; k++) m = fmaxf(m, lred[k*44 + tid]);
        sm_m[tid] = m;
    }
    __syncthreads();

    // ---- exp in registers, single psm write, per-u partial sums ----
    #pragma unroll
    for (int q = 0; q < 5; q++) {
        float mq = sm_m[ug*5 + q];
        float ls = 0.f;
        #pragma unroll
        for (int a = 0; a < 4; a++) {
            float e = __expf(acc[a][q] - mq);
            psm[(kg*4 + a)*44 + ug*5 + q] = e;
            ls += e;
        }
        lred[kg*44 + ug*5 + q] = ls;
    }
    __syncthreads();

    // ---- V chunk load (reuse Ks) + pl reduction ----
    #pragma unroll
    for (int it = 0; it < 8; it++) {
        int i = tid + it*128;
        int k = i >> 4, d4 = i & 15;
        Ks4[k*17 + d4] = Vg[((b*LL + k0 + k)*HH + h)*16 + d4];
    }
    if (tid < UU) {
        float s = 0.f;
        #pragma unroll
        for (int k = 0; k < 16; k++) s += lred[k*44 + tid];
        int pidx = (bh*K3_NCH + c)*UU + tid;
        g_pm[pidx] = sm_m[tid];
        g_pl[pidx] = s;
    }
    __syncthreads();

    // ---- AV ----
    {
        int dg = tid & 15, ugv = tid >> 4;
        float4 oacc[5];
        #pragma unroll
        for (int j = 0; j < 5; j++) oacc[j] = make_float4(0.f, 0.f, 0.f, 0.f);
        #pragma unroll 8
        for (int k = 0; k < K3_CHUNK; k++) {
            float4 vv = Ks4[k*17 + dg];
            float p[5];
            #pragma unroll
            for (int j = 0; j < 5; j++) p[j] = psm[k*44 + ugv*5 + j];
            #pragma unroll
            for (int j = 0; j < 5; j++) {
                oacc[j].x += p[j]*vv.x; oacc[j].y += p[j]*vv.y;
                oacc[j].z += p[j]*vv.z; oacc[j].w += p[j]*vv.w;
            }
        }
        float4* dst = (float4*)(g_pacc + ((size_t)(bh*K3_NCH + c)*UU)*DD);
        #pragma unroll
        for (int j = 0; j < 5; j++)
            dst[(ugv*5 + j)*16 + dg] = oacc[j];
    }
}

// ================= Kernel 3b: LSE combine (8 u per block, MLP-8) ====
__global__ void __launch_bounds__(512) k_combine() {
    int bh = blockIdx.x / 5;
    int u  = (blockIdx.x % 5)*8 + (threadIdx.x >> 6);
    int d  = threadIdx.x & 63;
    int base = bh*K3_NCH*UU + u;
    float m = -INFINITY;
    #pragma unroll
    for (int c = 0; c < K3_NCH; c++) m = fmaxf(m, g_pm[base + c*UU]);
    float ls = 0.f;
    float vacc[8];
    #pragma unroll
    for (int j = 0; j < 8; j++) vacc[j] = 0.f;
    #pragma unroll
    for (int c = 0; c < K3_NCH; c += 8) {
        float w[8], pl[8], pv[8];
        #pragma unroll
        for (int j = 0; j < 8; j++) w[j]  = __expf(g_pm[base + (c+j)*UU] - m);
        #pragma unroll
        for (int j = 0; j < 8; j++) pl[j] = g_pl[base + (c+j)*UU];
        #pragma unroll
        for (int j = 0; j < 8; j++) pv[j] = g_pacc[(size_t)(base + (c+j)*UU)*DD + d];
        #pragma unroll
        for (int j = 0; j < 8; j++) { ls += pl[j]*w[j]; vacc[j] += pv[j]*w[j]; }
    }
    float val = ((vacc[0]+vacc[1]) + (vacc[2]+vacc[3]))
              + ((vacc[4]+vacc[5]) + (vacc[6]+vacc[7]));
    g_upd[(bh*UU + u)*DD + d] = val / ls;
}

// ================= Kernel 4a: per-chunk sums of V along L (MLP-8) ====
__global__ void __launch_bounds__(512) k_csum(const float* __restrict__ V) {
    int b = blockIdx.x >> 5;
    int c = blockIdx.x & 31;
    int hd = threadIdx.x;
    const float* p = V + ((size_t)(b*LL + c*K4_CLEN))*512 + hd;
    float s0 = 0.f, s1 = 0.f, s2 = 0.f, s3 = 0.f;
    #pragma unroll
    for (int i = 0; i < K4_CLEN; i += 8) {
        float v0 = p[(i+0)*512], v1 = p[(i+1)*512];
        float v2 = p[(i+2)*512], v3 = p[(i+3)*512];
        float v4 = p[(i+4)*512], v5 = p[(i+5)*512];
        float v6 = p[(i+6)*512], v7 = p[(i+7)*512];
        s0 += v0 + v4; s1 += v1 + v5; s2 += v2 + v6; s3 += v3 + v7;
    }
    g_csum[(b*K4_NC + c)*512 + hd] = (s0 + s1) + (s2 + s3);
}

// ================= Kernel 4b: cumsum + scatter upd -> output (MLP-8 batches) ====
__global__ void __launch_bounds__(512) k_out(const float* __restrict__ V,
                                             float* __restrict__ out) {
    int b = blockIdx.x >> 5;
    int c = blockIdx.x & 31;
    int hd = threadIdx.x;
    int h = hd >> 6, d = hd & 63;
    float acc = 0.f;
    #pragma unroll
    for (int cc = 0; cc < K4_NC - 1; cc++) {
        float vv = g_csum[(b*K4_NC + cc)*512 + hd];
        if (cc < c) acc += vv;
    }
    const float* p = V   + ((size_t)(b*LL + c*K4_CLEN))*512 + hd;
    float*       q = out + ((size_t)(b*LL + c*K4_CLEN))*512 + hd;
    const int* sel = g_sel + (b*HH + h)*LL + c*K4_CLEN;
    #pragma unroll
    for (int i0 = 0; i0 < K4_CLEN; i0 += 8) {
        float v[8]; int se[8];
        #pragma unroll
        for (int j = 0; j < 8; j++) v[j] = p[(i0+j)*512];
        #pragma unroll
        for (int j = 0; j < 8; j++) se[j] = sel[i0+j];
        #pragma unroll
        for (int j = 0; j < 8; j++) {
            acc += v[j];
            float o = acc;
            if (se[j] >= 0) o = g_upd[((b*HH + h)*UU + se[j])*DD + d];
            q[(i0+j)*512] = o;
        }
    }
}

// ================= launch ====
extern "C" void kernel_launch(void* const* d_in, const int* in_sizes, int n_in,
                              void* d_out, int out_size) {
    const float* Q  = (const float*)d_in[0];
    const float* K  = (const float*)d_in[1];
    const float* V  = (const float*)d_in[2];
    const int* idx  = (const int*)d_in[3];
    float* out = (float*)d_out;

    cudaFuncSetAttribute(k_M, cudaFuncAttributeMaxDynamicSharedMemorySize, KM_SMEM);

    k_bin<<<LL/128, 128>>>(idx);
    k_M<<<BB*HH*(LL/KM_QT), KM_T, KM_SMEM>>>(Q, K);
    k_topk<<<BB*HH, 256>>>();
    dim3 g3(K3_NCH, BB*HH);
    k_attn_partial<<<g3, K3_T>>>(Q, K, V);
    k_combine<<<BB*HH*(UU/8), 512>>>();
    k_csum<<<BB*K4_NC, 512>>>(V);
    k_out<<<BB*K4_NC, 512>>>(V, out);
}